// round 8
// baseline (speedup 1.0000x reference)
#include <cuda_runtime.h>
#include <cuda_bf16.h>
#include <math.h>

#define N_NODES 40000
#define E_EDGES 1280000
#define S_DIM 64
#define V_DIM 16
#define R_DIM 32

#define TBINS 4096
#define RAW_ROWS 4098
#define RAW_COLS 160
#define PK_ROWS 4097
#define PK_COLS 320          // 1280 bytes/row

#define SIGBINS 2048         // sigmoid LUT over [-16, 16)
#define SRROW 176            // g_SrcRow floats per node (704 B)

// Per-node data
__device__ __align__(16) float g_Pa[N_NODES * S_DIM];
__device__ __align__(16) float g_SrcRow[N_NODES * SRROW];  // [Pb|scalars interleaved | vectors(48)]
// Distance tables
__device__ __align__(16) float g_raw[RAW_ROWS * RAW_COLS];
__device__ __align__(16) float g_tab[PK_ROWS * PK_COLS];
// Sigmoid LUT (val, slope)
__device__ __align__(16) float2 g_sig[SIGBINS];

__device__ __forceinline__ float silu_f(float x) {
    return x / (1.0f + __expf(-x));
}
__device__ __forceinline__ void red_add_v2(float* ptr, float x, float y) {
    asm volatile("red.global.v2.f32.add [%0], {%1, %2};"
                 :: "l"(ptr), "f"(x), "f"(y) : "memory");
}

// ---------------------------------------------------------------------------
__global__ void init_out_kernel(const float* __restrict__ scalars,
                                const float* __restrict__ vectors,
                                float* __restrict__ out) {
    const int NS4 = (N_NODES * S_DIM) / 4;
    const int NV4 = (N_NODES * V_DIM * 3) / 4;
    int i = blockIdx.x * blockDim.x + threadIdx.x;
    if (i < NS4) {
        reinterpret_cast<float4*>(out)[i] =
            reinterpret_cast<const float4*>(scalars)[i];
    } else if (i < NS4 + NV4) {
        reinterpret_cast<float4*>(out)[i] =
            reinterpret_cast<const float4*>(vectors)[i - NS4];
    }
}

// ---------------------------------------------------------------------------
// Sigmoid LUT builder
// ---------------------------------------------------------------------------
__global__ void sig_table_kernel() {
    int i = blockIdx.x * blockDim.x + threadIdx.x;
    if (i < SIGBINS) {
        float x0 = -16.0f + (float)i * (32.0f / SIGBINS);
        float x1 = -16.0f + (float)(i + 1) * (32.0f / SIGBINS);
        float v0 = 1.0f / (1.0f + expf(-x0));
        float v1 = 1.0f / (1.0f + expf(-x1));
        g_sig[i] = make_float2(v0, v1 - v0);
    }
}

// ---------------------------------------------------------------------------
// proj: Pa = ba1 + s@Wa1[0:64]; SrcRow = [Pb|scalars interleaved | vectors]
// ---------------------------------------------------------------------------
#define PROJ_NB 32
__global__ __launch_bounds__(256) void proj_kernel(
    const float* __restrict__ scalars,
    const float* __restrict__ vectors,
    const float* __restrict__ Wa1,
    const float* __restrict__ ba1) {
    __shared__ __align__(16) float sWi[64 * 128];
    __shared__ __align__(16) float sS[PROJ_NB * 64];

    const int tid = threadIdx.x;
    const int n0 = blockIdx.x * PROJ_NB;

    for (int idx = tid; idx < 64 * 128; idx += 256) {
        int k = idx >> 7, r = idx & 127, j = r >> 1, h = r & 1;
        sWi[idx] = Wa1[(h * 64 + k) * 64 + j];
    }
    for (int i = tid; i < PROJ_NB * 64; i += 256) sS[i] = scalars[n0 * 64 + i];
    __syncthreads();

    const int j = tid & 63;
    const int grp = tid >> 6;
    const float* sbase = &sS[grp * 8 * 64];

    float pa[8], pb[8];
    {
        const float b = __ldg(&ba1[j]);
#pragma unroll
        for (int nn = 0; nn < 8; nn++) { pa[nn] = b; pb[nn] = 0.0f; }
    }

#pragma unroll 4
    for (int k = 0; k < 64; k++) {
        float2 w = *reinterpret_cast<const float2*>(&sWi[k * 128 + 2 * j]);
#pragma unroll
        for (int nn = 0; nn < 8; nn++) {
            float s = sbase[nn * 64 + k];
            pa[nn] = fmaf(s, w.x, pa[nn]);
            pb[nn] = fmaf(s, w.y, pb[nn]);
        }
    }

#pragma unroll
    for (int nn = 0; nn < 8; nn++) {
        const int node = n0 + grp * 8 + nn;
        g_Pa[node * 64 + j] = pa[nn];
        int base = node * SRROW + (j >> 1) * 4 + (j & 1);
        g_SrcRow[base] = pb[nn];
        g_SrcRow[base + 2] = sbase[nn * 64 + j];
        if (j < 48)
            g_SrcRow[node * SRROW + 128 + j] = __ldg(&vectors[node * 48 + j]);
    }
}

// ---------------------------------------------------------------------------
// raw distance table
// ---------------------------------------------------------------------------
__global__ __launch_bounds__(160) void table_kernel(
    const float* __restrict__ W1, const float* __restrict__ b1,
    const float* __restrict__ W2, const float* __restrict__ b2,
    const float* __restrict__ Wa1) {
    __shared__ float rbf[32];
    __shared__ float h[32];
    const int row = blockIdx.x;
    const int tid = threadIdx.x;
    const float d = fminf((float)row, (float)TBINS) * (10.0f / TBINS);

    if (tid < 32) {
        float freq01 = 0.1f * (float)(tid + 1);
        float ds = fmaxf(d, 1e-8f);
        float bess;
        if (d < 1e-6f) bess = (float)M_PI * freq01;
        else           bess = sinpif(d * freq01) / ds;
        float cut = (d < 10.0f) ? 0.5f * (cospif(d * 0.1f) + 1.0f) : 0.0f;
        rbf[tid] = bess * cut;
    }
    __syncthreads();
    if (tid < 32) {
        float acc = b1[tid];
#pragma unroll 8
        for (int k = 0; k < 32; k++) acc = fmaf(rbf[k], W1[k * 32 + tid], acc);
        h[tid] = silu_f(acc);
    }
    __syncthreads();

    float outv;
    if (tid < 64) {
        float acc = b2[tid];
#pragma unroll 8
        for (int jj = 0; jj < 32; jj++) acc = fmaf(h[jj], W2[jj * 96 + tid], acc);
        outv = acc;
    } else if (tid < 128) {
        int c = tid - 64;
        float acc = 0.0f;
#pragma unroll 8
        for (int k = 0; k < 32; k++) acc = fmaf(rbf[k], Wa1[(128 + k) * 64 + c], acc);
        outv = acc;
    } else {
        int c = 64 + tid - 128;
        float acc = b2[c];
#pragma unroll 8
        for (int jj = 0; jj < 32; jj++) acc = fmaf(h[jj], W2[jj * 96 + c], acc);
        outv = acc;
    }
    g_raw[row * RAW_COLS + tid] = outv;
}

// ---------------------------------------------------------------------------
// pack raw -> (val, slope)
// ---------------------------------------------------------------------------
__global__ __launch_bounds__(320) void pack_kernel() {
    const int row = blockIdx.x;
    const int t = threadIdx.x;
    const float* r0 = g_raw + row * RAW_COLS;
    const float* r1 = r0 + RAW_COLS;
    float v;
    if (t < 128) {
        int j = t >> 2, k = t & 3;
        int col = 2 * j + (k & 1);
        v = (k < 2) ? r0[col] : (r1[col] - r0[col]);
    } else if (t < 256) {
        int u = t - 128;
        int j = u >> 2, k = u & 3;
        int col = 64 + 2 * j + (k & 1);
        v = (k < 2) ? r0[col] : (r1[col] - r0[col]);
    } else {
        int u = t - 256;
        int j = u >> 1, k = u & 1;
        int col = 128 + j;
        v = (k == 0) ? r0[col] : (r1[col] - r0[col]);
    }
    g_tab[row * PK_COLS + t] = v;
}

// ---------------------------------------------------------------------------
// edge kernel: Phase A lane-parallel geometry; Phase B broadcast + LUT math.
// ---------------------------------------------------------------------------
__global__ __launch_bounds__(256) void edge_kernel(
    const float* __restrict__ edge_vec,
    const int* __restrict__ ei,
    const float* __restrict__ Wa2,
    const float* __restrict__ ba2,
    float* __restrict__ out) {

    __shared__ __align__(16) float2 sSig[SIGBINS];   // 16 KB

    const int tid = threadIdx.x;
    const int warp = tid >> 5;
    const int lane = tid & 31;

    for (int i = tid; i < SIGBINS; i += 256) sSig[i] = g_sig[i];
    __syncthreads();

    const float ba2v = __ldg(&ba2[0]);
    const float wlo = __ldg(&Wa2[2 * lane]);
    const float whi = __ldg(&Wa2[2 * lane + 1]);

    const char* tabBase = (const char*)g_tab;
    const char* paBase = (const char*)g_Pa;
    const char* srBase = (const char*)g_SrcRow;
    char* outSBase = (char*)out;
    char* outVBase = (char*)(out + N_NODES * S_DIM);

    const unsigned laneA = lane * 16u;
    const unsigned laneB = 512u + lane * 16u;
    const unsigned laneC = 1024u + lane * 8u;
    const unsigned lane8 = lane * 8u;
    const unsigned lane16 = lane * 16u;
    const int i0 = 2 * lane;
    const int i1 = 2 * lane + 1;
    const int vi0 = (i0 < 48 ? i0 : 45) / 3, vc0 = (i0 < 48 ? i0 : 45) % 3;
    const int vi1 = (i1 < 48 ? i1 : 46) / 3, vc1 = (i1 < 48 ? i1 : 46) % 3;
    const unsigned laneV = (unsigned)i0 * 4u;
    const unsigned laneSV = 512u + laneV;            // vectors inside SrcRow

    const int NWT = E_EDGES / 32;

    for (int wt = blockIdx.x * 8 + warp; wt < NWT; wt += gridDim.x * 8) {
        const int e = wt * 32 + lane;

        // ---- Phase A ----
        float x = __ldg(&edge_vec[3 * e + 0]);
        float y = __ldg(&edge_vec[3 * e + 1]);
        float z = __ldg(&edge_vec[3 * e + 2]);
        int sL = __ldg(&ei[e]);
        int dL = __ldg(&ei[E_EDGES + e]);
        float d = sqrtf(fmaf(x, x, fmaf(y, y, z * z)));
        float iv = 1.0f / fmaxf(d, 1e-8f);
        float uxL = x * iv, uyL = y * iv, uzL = z * iv;
        float dn = d * ((float)TBINS / 10.0f);
        int bin = min((int)dn, TBINS);
        float wL = dn - (float)bin;
        unsigned rowOffL = (unsigned)bin * 1280u;
        unsigned dstOffL = (unsigned)dL * 256u;
        unsigned srcOffL = (unsigned)sL * (SRROW * 4u);   // 704 B
        unsigned vdOffL = (unsigned)dL * 192u;

        // ---- Phase B ----
#pragma unroll 4
        for (int t = 0; t < 32; t++) {
            float w = __shfl_sync(0xffffffffu, wL, t);
            float ux = __shfl_sync(0xffffffffu, uxL, t);
            float uy = __shfl_sync(0xffffffffu, uyL, t);
            float uz = __shfl_sync(0xffffffffu, uzL, t);
            unsigned rowOff = __shfl_sync(0xffffffffu, rowOffL, t);
            unsigned dstOff = __shfl_sync(0xffffffffu, dstOffL, t);
            unsigned srcOff = __shfl_sync(0xffffffffu, srcOffL, t);
            unsigned vdOff = __shfl_sync(0xffffffffu, vdOffL, t);

            float4 A = *reinterpret_cast<const float4*>(tabBase + rowOff + laneA);
            float4 B = *reinterpret_cast<const float4*>(tabBase + rowOff + laneB);
            float2 C = *reinterpret_cast<const float2*>(tabBase + rowOff + laneC);
            float2 Pa = *reinterpret_cast<const float2*>(paBase + dstOff + lane8);
            float4 SR = *reinterpret_cast<const float4*>(srBase + srcOff + lane16);

            float f0 = fmaf(w, A.z, A.x);
            float f1 = fmaf(w, A.w, A.y);
            float p0 = fmaf(w, B.z, B.x);
            float p1 = fmaf(w, B.w, B.y);
            float f2 = fmaf(w, C.y, C.x);

            float a0 = Pa.x + SR.x + p0;
            float a1 = Pa.y + SR.y + p1;

            // silu via sigmoid LUT
            float t0 = fminf(fmaxf(fmaf(a0, (float)SIGBINS / 32.0f,
                                        (float)SIGBINS / 2.0f), 0.0f), (float)(SIGBINS - 1));
            float t1 = fminf(fmaxf(fmaf(a1, (float)SIGBINS / 32.0f,
                                        (float)SIGBINS / 2.0f), 0.0f), (float)(SIGBINS - 1));
            int b0i = (int)t0;
            int b1i = (int)t1;
            float2 sv0 = sSig[b0i];
            float2 sv1 = sSig[b1i];
            float sg0 = fmaf(t0 - (float)b0i, sv0.y, sv0.x);
            float sg1 = fmaf(t1 - (float)b1i, sv1.y, sv1.x);

            float p = fmaf(a0 * sg0, wlo, (a1 * sg1) * whi);
            p += __shfl_xor_sync(0xffffffffu, p, 16);
            p += __shfl_xor_sync(0xffffffffu, p, 8);
            p += __shfl_xor_sync(0xffffffffu, p, 4);
            p += __shfl_xor_sync(0xffffffffu, p, 2);
            p += __shfl_xor_sync(0xffffffffu, p, 1);

            // attention sigmoid via LUT
            float ta = fminf(fmaxf(fmaf(p + ba2v, (float)SIGBINS / 32.0f,
                                        (float)SIGBINS / 2.0f), 0.0f), (float)(SIGBINS - 1));
            int bai = (int)ta;
            float2 sva = sSig[bai];
            float att = fmaf(ta - (float)bai, sva.y, sva.x);

            // scalar message
            red_add_v2(reinterpret_cast<float*>(outSBase + dstOff + lane8),
                       att * SR.z * f0, att * SR.w * f1);

            // vector message
            float vf0 = __shfl_sync(0xffffffffu, f2, vi0);
            float vg0 = __shfl_sync(0xffffffffu, f2, vi0 + 16);
            float vf1 = __shfl_sync(0xffffffffu, f2, vi1);
            float vg1 = __shfl_sync(0xffffffffu, f2, vi1 + 16);
            if (lane < 24) {
                float2 vv = *reinterpret_cast<const float2*>(srBase + srcOff + laneSV);
                float shc0 = (vc0 == 0) ? uy : ((vc0 == 1) ? uz : ux);
                float shc1 = (vc1 == 0) ? uy : ((vc1 == 1) ? uz : ux);
                float m0 = att * fmaf(vv.x, vf0, vg0 * shc0);
                float m1 = att * fmaf(vv.y, vf1, vg1 * shc1);
                red_add_v2(reinterpret_cast<float*>(outVBase + vdOff + laneV), m0, m1);
            }
        }
    }
}

// ---------------------------------------------------------------------------
extern "C" void kernel_launch(void* const* d_in, const int* in_sizes, int n_in,
                              void* d_out, int out_size) {
    const float* scalars = (const float*)d_in[0];
    const float* vectors = (const float*)d_in[1];
    const float* edge_vec = (const float*)d_in[2];
    const float* W1 = (const float*)d_in[3];
    const float* b1 = (const float*)d_in[4];
    const float* W2 = (const float*)d_in[5];
    const float* b2 = (const float*)d_in[6];
    const float* Wa1 = (const float*)d_in[7];
    const float* ba1 = (const float*)d_in[8];
    const float* Wa2 = (const float*)d_in[9];
    const float* ba2 = (const float*)d_in[10];
    const int* ei = (const int*)d_in[11];
    float* out = (float*)d_out;

    const int TOT4 = (N_NODES * S_DIM + N_NODES * V_DIM * 3) / 4;
    init_out_kernel<<<(TOT4 + 255) / 256, 256>>>(scalars, vectors, out);
    sig_table_kernel<<<SIGBINS / 256, 256>>>();
    table_kernel<<<RAW_ROWS, 160>>>(W1, b1, W2, b2, Wa1);
    pack_kernel<<<PK_ROWS, 320>>>();
    proj_kernel<<<N_NODES / PROJ_NB, 256>>>(scalars, vectors, Wa1, ba1);
    edge_kernel<<<2500, 256>>>(edge_vec, ei, Wa2, ba2, out);
}

// round 9
// speedup vs baseline: 1.3396x; 1.3396x over previous
#include <cuda_runtime.h>
#include <cuda_bf16.h>
#include <math.h>

#define N_NODES 40000
#define E_EDGES 1280000
#define S_DIM 64
#define V_DIM 16
#define R_DIM 32

#define TBINS 4096
#define RAW_ROWS 4098
#define RAW_COLS 160
#define PK_ROWS 4097
#define PK_COLS 320          // 1280 bytes/row

#define SRROW 176            // g_SrcRow floats per node (704 B)

// Per-node data
__device__ __align__(16) float g_Pa[N_NODES * S_DIM];
__device__ __align__(16) float g_SrcRow[N_NODES * SRROW];  // [Pb|scalars interleaved | vectors(48)]
// Distance tables
__device__ __align__(16) float g_raw[RAW_ROWS * RAW_COLS];
__device__ __align__(16) float g_tab[PK_ROWS * PK_COLS];

__device__ __forceinline__ float silu_f(float x) {
    return x / (1.0f + __expf(-x));
}
__device__ __forceinline__ void red_add_v2(float* ptr, float x, float y) {
    asm volatile("red.global.v2.f32.add [%0], {%1, %2};"
                 :: "l"(ptr), "f"(x), "f"(y) : "memory");
}

// ---------------------------------------------------------------------------
__global__ void init_out_kernel(const float* __restrict__ scalars,
                                const float* __restrict__ vectors,
                                float* __restrict__ out) {
    const int NS4 = (N_NODES * S_DIM) / 4;
    const int NV4 = (N_NODES * V_DIM * 3) / 4;
    int i = blockIdx.x * blockDim.x + threadIdx.x;
    if (i < NS4) {
        reinterpret_cast<float4*>(out)[i] =
            reinterpret_cast<const float4*>(scalars)[i];
    } else if (i < NS4 + NV4) {
        reinterpret_cast<float4*>(out)[i] =
            reinterpret_cast<const float4*>(vectors)[i - NS4];
    }
}

// ---------------------------------------------------------------------------
// proj: Pa = ba1 + s@Wa1[0:64]; SrcRow = [Pb|scalars interleaved | vectors]
// ---------------------------------------------------------------------------
#define PROJ_NB 32
__global__ __launch_bounds__(256) void proj_kernel(
    const float* __restrict__ scalars,
    const float* __restrict__ vectors,
    const float* __restrict__ Wa1,
    const float* __restrict__ ba1) {
    __shared__ __align__(16) float sWi[64 * 128];
    __shared__ __align__(16) float sS[PROJ_NB * 64];

    const int tid = threadIdx.x;
    const int n0 = blockIdx.x * PROJ_NB;

    for (int idx = tid; idx < 64 * 128; idx += 256) {
        int k = idx >> 7, r = idx & 127, j = r >> 1, h = r & 1;
        sWi[idx] = Wa1[(h * 64 + k) * 64 + j];
    }
    for (int i = tid; i < PROJ_NB * 64; i += 256) sS[i] = scalars[n0 * 64 + i];
    __syncthreads();

    const int j = tid & 63;
    const int grp = tid >> 6;
    const float* sbase = &sS[grp * 8 * 64];

    float pa[8], pb[8];
    {
        const float b = __ldg(&ba1[j]);
#pragma unroll
        for (int nn = 0; nn < 8; nn++) { pa[nn] = b; pb[nn] = 0.0f; }
    }

#pragma unroll 4
    for (int k = 0; k < 64; k++) {
        float2 w = *reinterpret_cast<const float2*>(&sWi[k * 128 + 2 * j]);
#pragma unroll
        for (int nn = 0; nn < 8; nn++) {
            float s = sbase[nn * 64 + k];
            pa[nn] = fmaf(s, w.x, pa[nn]);
            pb[nn] = fmaf(s, w.y, pb[nn]);
        }
    }

#pragma unroll
    for (int nn = 0; nn < 8; nn++) {
        const int node = n0 + grp * 8 + nn;
        g_Pa[node * 64 + j] = pa[nn];
        int base = node * SRROW + (j >> 1) * 4 + (j & 1);
        g_SrcRow[base] = pb[nn];
        g_SrcRow[base + 2] = sbase[nn * 64 + j];
        if (j < 48)
            g_SrcRow[node * SRROW + 128 + j] = __ldg(&vectors[node * 48 + j]);
    }
}

// ---------------------------------------------------------------------------
// raw distance table
// ---------------------------------------------------------------------------
__global__ __launch_bounds__(160) void table_kernel(
    const float* __restrict__ W1, const float* __restrict__ b1,
    const float* __restrict__ W2, const float* __restrict__ b2,
    const float* __restrict__ Wa1) {
    __shared__ float rbf[32];
    __shared__ float h[32];
    const int row = blockIdx.x;
    const int tid = threadIdx.x;
    const float d = fminf((float)row, (float)TBINS) * (10.0f / TBINS);

    if (tid < 32) {
        float freq01 = 0.1f * (float)(tid + 1);
        float ds = fmaxf(d, 1e-8f);
        float bess;
        if (d < 1e-6f) bess = (float)M_PI * freq01;
        else           bess = sinpif(d * freq01) / ds;
        float cut = (d < 10.0f) ? 0.5f * (cospif(d * 0.1f) + 1.0f) : 0.0f;
        rbf[tid] = bess * cut;
    }
    __syncthreads();
    if (tid < 32) {
        float acc = b1[tid];
#pragma unroll 8
        for (int k = 0; k < 32; k++) acc = fmaf(rbf[k], W1[k * 32 + tid], acc);
        h[tid] = silu_f(acc);
    }
    __syncthreads();

    float outv;
    if (tid < 64) {
        float acc = b2[tid];
#pragma unroll 8
        for (int jj = 0; jj < 32; jj++) acc = fmaf(h[jj], W2[jj * 96 + tid], acc);
        outv = acc;
    } else if (tid < 128) {
        int c = tid - 64;
        float acc = 0.0f;
#pragma unroll 8
        for (int k = 0; k < 32; k++) acc = fmaf(rbf[k], Wa1[(128 + k) * 64 + c], acc);
        outv = acc;
    } else {
        int c = 64 + tid - 128;
        float acc = b2[c];
#pragma unroll 8
        for (int jj = 0; jj < 32; jj++) acc = fmaf(h[jj], W2[jj * 96 + c], acc);
        outv = acc;
    }
    g_raw[row * RAW_COLS + tid] = outv;
}

// ---------------------------------------------------------------------------
// pack raw -> (val, slope)
// ---------------------------------------------------------------------------
__global__ __launch_bounds__(320) void pack_kernel() {
    const int row = blockIdx.x;
    const int t = threadIdx.x;
    const float* r0 = g_raw + row * RAW_COLS;
    const float* r1 = r0 + RAW_COLS;
    float v;
    if (t < 128) {
        int j = t >> 2, k = t & 3;
        int col = 2 * j + (k & 1);
        v = (k < 2) ? r0[col] : (r1[col] - r0[col]);
    } else if (t < 256) {
        int u = t - 128;
        int j = u >> 2, k = u & 3;
        int col = 64 + 2 * j + (k & 1);
        v = (k < 2) ? r0[col] : (r1[col] - r0[col]);
    } else {
        int u = t - 256;
        int j = u >> 1, k = u & 1;
        int col = 128 + j;
        v = (k == 0) ? r0[col] : (r1[col] - r0[col]);
    }
    g_tab[row * PK_COLS + t] = v;
}

// ---------------------------------------------------------------------------
// edge kernel: Phase A lane-parallel geometry -> smem param slab;
// Phase B: broadcast LDS.128 reads + MUFU math + scatter.
// ---------------------------------------------------------------------------
__global__ __launch_bounds__(256) void edge_kernel(
    const float* __restrict__ edge_vec,
    const int* __restrict__ ei,
    const float* __restrict__ Wa2,
    const float* __restrict__ ba2,
    float* __restrict__ out) {

    // per-warp param slab: [warp][edge][8 floats] = 8 KB total
    __shared__ __align__(16) float sParam[8][32][8];

    const int tid = threadIdx.x;
    const int warp = tid >> 5;
    const int lane = tid & 31;

    const float ba2v = __ldg(&ba2[0]);
    const float wlo = __ldg(&Wa2[2 * lane]);
    const float whi = __ldg(&Wa2[2 * lane + 1]);

    const char* tabBase = (const char*)g_tab;
    const char* paBase = (const char*)g_Pa;
    const char* srBase = (const char*)g_SrcRow;
    char* outSBase = (char*)out;
    char* outVBase = (char*)(out + N_NODES * S_DIM);

    const unsigned laneA = lane * 16u;
    const unsigned laneB = 512u + lane * 16u;
    const unsigned laneC = 1024u + lane * 8u;
    const unsigned lane8 = lane * 8u;
    const unsigned lane16 = lane * 16u;
    const int i0 = 2 * lane;
    const int i1 = 2 * lane + 1;
    const int vi0 = (i0 < 48 ? i0 : 45) / 3, vc0 = (i0 < 48 ? i0 : 45) % 3;
    const int vi1 = (i1 < 48 ? i1 : 46) / 3, vc1 = (i1 < 48 ? i1 : 46) % 3;
    const unsigned laneV = (unsigned)i0 * 4u;
    const unsigned laneSV = 512u + laneV;            // vectors inside SrcRow

    const int NWT = E_EDGES / 32;

    for (int wt = blockIdx.x * 8 + warp; wt < NWT; wt += gridDim.x * 8) {
        const int e = wt * 32 + lane;

        // ---- Phase A: lane-parallel geometry ----
        float x = __ldg(&edge_vec[3 * e + 0]);
        float y = __ldg(&edge_vec[3 * e + 1]);
        float z = __ldg(&edge_vec[3 * e + 2]);
        int sL = __ldg(&ei[e]);
        int dL = __ldg(&ei[E_EDGES + e]);
        float d = sqrtf(fmaf(x, x, fmaf(y, y, z * z)));
        float iv = 1.0f / fmaxf(d, 1e-8f);
        float dn = d * ((float)TBINS / 10.0f);
        int bin = min((int)dn, TBINS);

        __syncwarp();   // Phase B of previous tile done reading sParam
        {
            float4 p0 = make_float4(dn - (float)bin, x * iv, y * iv, z * iv);
            float4 p1;
            p1.x = __uint_as_float((unsigned)bin * 1280u);
            p1.y = __uint_as_float((unsigned)dL * 256u);
            p1.z = __uint_as_float((unsigned)sL * (SRROW * 4u));
            p1.w = __uint_as_float((unsigned)dL * 192u);
            *reinterpret_cast<float4*>(&sParam[warp][lane][0]) = p0;
            *reinterpret_cast<float4*>(&sParam[warp][lane][4]) = p1;
        }
        __syncwarp();

        // ---- Phase B ----
#pragma unroll 4
        for (int t = 0; t < 32; t++) {
            float4 P0 = *reinterpret_cast<const float4*>(&sParam[warp][t][0]);
            float4 P1 = *reinterpret_cast<const float4*>(&sParam[warp][t][4]);
            float w = P0.x, ux = P0.y, uy = P0.z, uz = P0.w;
            unsigned rowOff = __float_as_uint(P1.x);
            unsigned dstOff = __float_as_uint(P1.y);
            unsigned srcOff = __float_as_uint(P1.z);
            unsigned vdOff = __float_as_uint(P1.w);

            float4 A = *reinterpret_cast<const float4*>(tabBase + rowOff + laneA);
            float4 B = *reinterpret_cast<const float4*>(tabBase + rowOff + laneB);
            float2 C = *reinterpret_cast<const float2*>(tabBase + rowOff + laneC);
            float2 Pa = *reinterpret_cast<const float2*>(paBase + dstOff + lane8);
            float4 SR = *reinterpret_cast<const float4*>(srBase + srcOff + lane16);

            float f0 = fmaf(w, A.z, A.x);
            float f1 = fmaf(w, A.w, A.y);
            float p0 = fmaf(w, B.z, B.x);
            float p1 = fmaf(w, B.w, B.y);
            float f2 = fmaf(w, C.y, C.x);

            float a0 = Pa.x + SR.x + p0;
            float a1 = Pa.y + SR.y + p1;
            float p = fmaf(silu_f(a0), wlo, silu_f(a1) * whi);
            p += __shfl_xor_sync(0xffffffffu, p, 16);
            p += __shfl_xor_sync(0xffffffffu, p, 8);
            p += __shfl_xor_sync(0xffffffffu, p, 4);
            p += __shfl_xor_sync(0xffffffffu, p, 2);
            p += __shfl_xor_sync(0xffffffffu, p, 1);
            float att = 1.0f / (1.0f + __expf(-(p + ba2v)));

            // scalar message
            red_add_v2(reinterpret_cast<float*>(outSBase + dstOff + lane8),
                       att * SR.z * f0, att * SR.w * f1);

            // vector message
            float vf0 = __shfl_sync(0xffffffffu, f2, vi0);
            float vg0 = __shfl_sync(0xffffffffu, f2, vi0 + 16);
            float vf1 = __shfl_sync(0xffffffffu, f2, vi1);
            float vg1 = __shfl_sync(0xffffffffu, f2, vi1 + 16);
            if (lane < 24) {
                float2 vv = *reinterpret_cast<const float2*>(srBase + srcOff + laneSV);
                float shc0 = (vc0 == 0) ? uy : ((vc0 == 1) ? uz : ux);
                float shc1 = (vc1 == 0) ? uy : ((vc1 == 1) ? uz : ux);
                float m0 = att * fmaf(vv.x, vf0, vg0 * shc0);
                float m1 = att * fmaf(vv.y, vf1, vg1 * shc1);
                red_add_v2(reinterpret_cast<float*>(outVBase + vdOff + laneV), m0, m1);
            }
        }
    }
}

// ---------------------------------------------------------------------------
extern "C" void kernel_launch(void* const* d_in, const int* in_sizes, int n_in,
                              void* d_out, int out_size) {
    const float* scalars = (const float*)d_in[0];
    const float* vectors = (const float*)d_in[1];
    const float* edge_vec = (const float*)d_in[2];
    const float* W1 = (const float*)d_in[3];
    const float* b1 = (const float*)d_in[4];
    const float* W2 = (const float*)d_in[5];
    const float* b2 = (const float*)d_in[6];
    const float* Wa1 = (const float*)d_in[7];
    const float* ba1 = (const float*)d_in[8];
    const float* Wa2 = (const float*)d_in[9];
    const float* ba2 = (const float*)d_in[10];
    const int* ei = (const int*)d_in[11];
    float* out = (float*)d_out;

    const int TOT4 = (N_NODES * S_DIM + N_NODES * V_DIM * 3) / 4;
    init_out_kernel<<<(TOT4 + 255) / 256, 256>>>(scalars, vectors, out);
    table_kernel<<<RAW_ROWS, 160>>>(W1, b1, W2, b2, Wa1);
    pack_kernel<<<PK_ROWS, 320>>>();
    proj_kernel<<<N_NODES / PROJ_NB, 256>>>(scalars, vectors, Wa1, ba1);
    edge_kernel<<<2500, 256>>>(edge_vec, ei, Wa2, ba2, out);
}

// round 10
// speedup vs baseline: 1.3869x; 1.0353x over previous
#include <cuda_runtime.h>
#include <cuda_bf16.h>
#include <cuda_fp16.h>
#include <math.h>

#define N_NODES 40000
#define E_EDGES 1280000
#define S_DIM 64
#define V_DIM 16
#define R_DIM 32

#define TBINS 4096
#define RAW_ROWS 4098
#define RAW_COLS 160
#define PK_ROWS 4097
#define PK_COLS 320          // halfs per row -> 640 bytes/row

#define SRROW 176            // g_SrcRow floats per node (704 B)

// Per-node data
__device__ __align__(16) float g_Pa[N_NODES * S_DIM];
__device__ __align__(16) float g_SrcRow[N_NODES * SRROW];  // [Pb|scalars interleaved | vectors(48)]
// Distance tables
__device__ __align__(16) float g_raw[RAW_ROWS * RAW_COLS];
__device__ __align__(16) __half g_tabh[PK_ROWS * PK_COLS]; // packed fp16 val/slope

__device__ __forceinline__ float silu_f(float x) {
    return x / (1.0f + __expf(-x));
}
__device__ __forceinline__ void red_add_v2(float* ptr, float x, float y) {
    asm volatile("red.global.v2.f32.add [%0], {%1, %2};"
                 :: "l"(ptr), "f"(x), "f"(y) : "memory");
}

// ---------------------------------------------------------------------------
__global__ void init_out_kernel(const float* __restrict__ scalars,
                                const float* __restrict__ vectors,
                                float* __restrict__ out) {
    const int NS4 = (N_NODES * S_DIM) / 4;
    const int NV4 = (N_NODES * V_DIM * 3) / 4;
    int i = blockIdx.x * blockDim.x + threadIdx.x;
    if (i < NS4) {
        reinterpret_cast<float4*>(out)[i] =
            reinterpret_cast<const float4*>(scalars)[i];
    } else if (i < NS4 + NV4) {
        reinterpret_cast<float4*>(out)[i] =
            reinterpret_cast<const float4*>(vectors)[i - NS4];
    }
}

// ---------------------------------------------------------------------------
// proj: Pa = ba1 + s@Wa1[0:64]; SrcRow = [Pb|scalars interleaved | vectors]
// ---------------------------------------------------------------------------
#define PROJ_NB 32
__global__ __launch_bounds__(256) void proj_kernel(
    const float* __restrict__ scalars,
    const float* __restrict__ vectors,
    const float* __restrict__ Wa1,
    const float* __restrict__ ba1) {
    __shared__ __align__(16) float sWi[64 * 128];
    __shared__ __align__(16) float sS[PROJ_NB * 64];

    const int tid = threadIdx.x;
    const int n0 = blockIdx.x * PROJ_NB;

    for (int idx = tid; idx < 64 * 128; idx += 256) {
        int k = idx >> 7, r = idx & 127, j = r >> 1, h = r & 1;
        sWi[idx] = Wa1[(h * 64 + k) * 64 + j];
    }
    for (int i = tid; i < PROJ_NB * 64; i += 256) sS[i] = scalars[n0 * 64 + i];
    __syncthreads();

    const int j = tid & 63;
    const int grp = tid >> 6;
    const float* sbase = &sS[grp * 8 * 64];

    float pa[8], pb[8];
    {
        const float b = __ldg(&ba1[j]);
#pragma unroll
        for (int nn = 0; nn < 8; nn++) { pa[nn] = b; pb[nn] = 0.0f; }
    }

#pragma unroll 4
    for (int k = 0; k < 64; k++) {
        float2 w = *reinterpret_cast<const float2*>(&sWi[k * 128 + 2 * j]);
#pragma unroll
        for (int nn = 0; nn < 8; nn++) {
            float s = sbase[nn * 64 + k];
            pa[nn] = fmaf(s, w.x, pa[nn]);
            pb[nn] = fmaf(s, w.y, pb[nn]);
        }
    }

#pragma unroll
    for (int nn = 0; nn < 8; nn++) {
        const int node = n0 + grp * 8 + nn;
        g_Pa[node * 64 + j] = pa[nn];
        int base = node * SRROW + (j >> 1) * 4 + (j & 1);
        g_SrcRow[base] = pb[nn];
        g_SrcRow[base + 2] = sbase[nn * 64 + j];
        if (j < 48)
            g_SrcRow[node * SRROW + 128 + j] = __ldg(&vectors[node * 48 + j]);
    }
}

// ---------------------------------------------------------------------------
// raw distance table (fp32)
// ---------------------------------------------------------------------------
__global__ __launch_bounds__(160) void table_kernel(
    const float* __restrict__ W1, const float* __restrict__ b1,
    const float* __restrict__ W2, const float* __restrict__ b2,
    const float* __restrict__ Wa1) {
    __shared__ float rbf[32];
    __shared__ float h[32];
    const int row = blockIdx.x;
    const int tid = threadIdx.x;
    const float d = fminf((float)row, (float)TBINS) * (10.0f / TBINS);

    if (tid < 32) {
        float freq01 = 0.1f * (float)(tid + 1);
        float ds = fmaxf(d, 1e-8f);
        float bess;
        if (d < 1e-6f) bess = (float)M_PI * freq01;
        else           bess = sinpif(d * freq01) / ds;
        float cut = (d < 10.0f) ? 0.5f * (cospif(d * 0.1f) + 1.0f) : 0.0f;
        rbf[tid] = bess * cut;
    }
    __syncthreads();
    if (tid < 32) {
        float acc = b1[tid];
#pragma unroll 8
        for (int k = 0; k < 32; k++) acc = fmaf(rbf[k], W1[k * 32 + tid], acc);
        h[tid] = silu_f(acc);
    }
    __syncthreads();

    float outv;
    if (tid < 64) {
        float acc = b2[tid];
#pragma unroll 8
        for (int jj = 0; jj < 32; jj++) acc = fmaf(h[jj], W2[jj * 96 + tid], acc);
        outv = acc;
    } else if (tid < 128) {
        int c = tid - 64;
        float acc = 0.0f;
#pragma unroll 8
        for (int k = 0; k < 32; k++) acc = fmaf(rbf[k], Wa1[(128 + k) * 64 + c], acc);
        outv = acc;
    } else {
        int c = 64 + tid - 128;
        float acc = b2[c];
#pragma unroll 8
        for (int jj = 0; jj < 32; jj++) acc = fmaf(h[jj], W2[jj * 96 + c], acc);
        outv = acc;
    }
    g_raw[row * RAW_COLS + tid] = outv;
}

// ---------------------------------------------------------------------------
// pack raw -> fp16 (val, slope) rows (640 B/row).
// Row layout (half index):
//  A: j=0..31 -> [j*4 + 0,1] = val(2j),val(2j+1); [j*4 + 2,3] = slope(2j),slope(2j+1)
//  B: 128 + same for raw cols 64..127
//  C: 256 + j*2 + {0,1} = val/slope for raw col 128+j
// ---------------------------------------------------------------------------
__global__ __launch_bounds__(320) void pack_kernel() {
    const int row = blockIdx.x;
    const int t = threadIdx.x;
    const float* r0 = g_raw + row * RAW_COLS;
    const float* r1 = r0 + RAW_COLS;
    float v;
    if (t < 128) {
        int j = t >> 2, k = t & 3;
        int col = 2 * j + (k & 1);
        v = (k < 2) ? r0[col] : (r1[col] - r0[col]);
    } else if (t < 256) {
        int u = t - 128;
        int j = u >> 2, k = u & 3;
        int col = 64 + 2 * j + (k & 1);
        v = (k < 2) ? r0[col] : (r1[col] - r0[col]);
    } else {
        int u = t - 256;
        int j = u >> 1, k = u & 1;
        int col = 128 + j;
        v = (k == 0) ? r0[col] : (r1[col] - r0[col]);
    }
    g_tabh[row * PK_COLS + t] = __float2half(v);
}

// ---------------------------------------------------------------------------
// edge kernel: Phase A lane-parallel geometry -> smem param slab;
// Phase B: broadcast LDS.128 params + fp16 table + scatter.
// ---------------------------------------------------------------------------
__global__ __launch_bounds__(256) void edge_kernel(
    const float* __restrict__ edge_vec,
    const int* __restrict__ ei,
    const float* __restrict__ Wa2,
    const float* __restrict__ ba2,
    float* __restrict__ out) {

    __shared__ __align__(16) float sParam[8][32][8];   // 8 KB

    const int tid = threadIdx.x;
    const int warp = tid >> 5;
    const int lane = tid & 31;

    const float ba2v = __ldg(&ba2[0]);
    const float wlo = __ldg(&Wa2[2 * lane]);
    const float whi = __ldg(&Wa2[2 * lane + 1]);

    const char* tabBase = (const char*)g_tabh;
    const char* paBase = (const char*)g_Pa;
    const char* srBase = (const char*)g_SrcRow;
    char* outSBase = (char*)out;
    char* outVBase = (char*)(out + N_NODES * S_DIM);

    const unsigned laneA = lane * 8u;           // 8 B: half2 val + half2 slope
    const unsigned laneB = 256u + lane * 8u;
    const unsigned laneC = 512u + lane * 4u;    // 4 B: half val + half slope
    const unsigned lane8 = lane * 8u;
    const unsigned lane16 = lane * 16u;
    const int i0 = 2 * lane;
    const int i1 = 2 * lane + 1;
    const int vi0 = (i0 < 48 ? i0 : 45) / 3, vc0 = (i0 < 48 ? i0 : 45) % 3;
    const int vi1 = (i1 < 48 ? i1 : 46) / 3, vc1 = (i1 < 48 ? i1 : 46) % 3;
    const unsigned laneV = (unsigned)i0 * 4u;
    const unsigned laneSV = 512u + laneV;       // vectors inside SrcRow

    const int NWT = E_EDGES / 32;

    for (int wt = blockIdx.x * 8 + warp; wt < NWT; wt += gridDim.x * 8) {
        const int e = wt * 32 + lane;

        // ---- Phase A ----
        float x = __ldg(&edge_vec[3 * e + 0]);
        float y = __ldg(&edge_vec[3 * e + 1]);
        float z = __ldg(&edge_vec[3 * e + 2]);
        int sL = __ldg(&ei[e]);
        int dL = __ldg(&ei[E_EDGES + e]);
        float d = sqrtf(fmaf(x, x, fmaf(y, y, z * z)));
        float iv = 1.0f / fmaxf(d, 1e-8f);
        float dn = d * ((float)TBINS / 10.0f);
        int bin = min((int)dn, TBINS);

        __syncwarp();
        {
            float4 p0 = make_float4(dn - (float)bin, x * iv, y * iv, z * iv);
            float4 p1;
            p1.x = __uint_as_float((unsigned)bin * 640u);
            p1.y = __uint_as_float((unsigned)dL * 256u);
            p1.z = __uint_as_float((unsigned)sL * (SRROW * 4u));
            p1.w = __uint_as_float((unsigned)dL * 192u);
            *reinterpret_cast<float4*>(&sParam[warp][lane][0]) = p0;
            *reinterpret_cast<float4*>(&sParam[warp][lane][4]) = p1;
        }
        __syncwarp();

        // ---- Phase B ----
#pragma unroll 4
        for (int t = 0; t < 32; t++) {
            float4 P0 = *reinterpret_cast<const float4*>(&sParam[warp][t][0]);
            float4 P1 = *reinterpret_cast<const float4*>(&sParam[warp][t][4]);
            float w = P0.x, ux = P0.y, uy = P0.z, uz = P0.w;
            unsigned rowOff = __float_as_uint(P1.x);
            unsigned dstOff = __float_as_uint(P1.y);
            unsigned srcOff = __float_as_uint(P1.z);
            unsigned vdOff = __float_as_uint(P1.w);

            uint2 Araw = *reinterpret_cast<const uint2*>(tabBase + rowOff + laneA);
            uint2 Braw = *reinterpret_cast<const uint2*>(tabBase + rowOff + laneB);
            unsigned Craw = *reinterpret_cast<const unsigned*>(tabBase + rowOff + laneC);
            float2 Pa = *reinterpret_cast<const float2*>(paBase + dstOff + lane8);
            float4 SR = *reinterpret_cast<const float4*>(srBase + srcOff + lane16);

            float2 Av = __half22float2(*reinterpret_cast<const __half2*>(&Araw.x));
            float2 As = __half22float2(*reinterpret_cast<const __half2*>(&Araw.y));
            float2 Bv = __half22float2(*reinterpret_cast<const __half2*>(&Braw.x));
            float2 Bs = __half22float2(*reinterpret_cast<const __half2*>(&Braw.y));
            float2 Cv = __half22float2(*reinterpret_cast<const __half2*>(&Craw));

            float f0 = fmaf(w, As.x, Av.x);
            float f1 = fmaf(w, As.y, Av.y);
            float p0 = fmaf(w, Bs.x, Bv.x);
            float p1 = fmaf(w, Bs.y, Bv.y);
            float f2 = fmaf(w, Cv.y, Cv.x);

            float a0 = Pa.x + SR.x + p0;
            float a1 = Pa.y + SR.y + p1;
            float p = fmaf(silu_f(a0), wlo, silu_f(a1) * whi);
            p += __shfl_xor_sync(0xffffffffu, p, 16);
            p += __shfl_xor_sync(0xffffffffu, p, 8);
            p += __shfl_xor_sync(0xffffffffu, p, 4);
            p += __shfl_xor_sync(0xffffffffu, p, 2);
            p += __shfl_xor_sync(0xffffffffu, p, 1);
            float att = 1.0f / (1.0f + __expf(-(p + ba2v)));

            // scalar message
            red_add_v2(reinterpret_cast<float*>(outSBase + dstOff + lane8),
                       att * SR.z * f0, att * SR.w * f1);

            // vector message
            float vf0 = __shfl_sync(0xffffffffu, f2, vi0);
            float vg0 = __shfl_sync(0xffffffffu, f2, vi0 + 16);
            float vf1 = __shfl_sync(0xffffffffu, f2, vi1);
            float vg1 = __shfl_sync(0xffffffffu, f2, vi1 + 16);
            if (lane < 24) {
                float2 vv = *reinterpret_cast<const float2*>(srBase + srcOff + laneSV);
                float shc0 = (vc0 == 0) ? uy : ((vc0 == 1) ? uz : ux);
                float shc1 = (vc1 == 0) ? uy : ((vc1 == 1) ? uz : ux);
                float m0 = att * fmaf(vv.x, vf0, vg0 * shc0);
                float m1 = att * fmaf(vv.y, vf1, vg1 * shc1);
                red_add_v2(reinterpret_cast<float*>(outVBase + vdOff + laneV), m0, m1);
            }
        }
    }
}

// ---------------------------------------------------------------------------
extern "C" void kernel_launch(void* const* d_in, const int* in_sizes, int n_in,
                              void* d_out, int out_size) {
    const float* scalars = (const float*)d_in[0];
    const float* vectors = (const float*)d_in[1];
    const float* edge_vec = (const float*)d_in[2];
    const float* W1 = (const float*)d_in[3];
    const float* b1 = (const float*)d_in[4];
    const float* W2 = (const float*)d_in[5];
    const float* b2 = (const float*)d_in[6];
    const float* Wa1 = (const float*)d_in[7];
    const float* ba1 = (const float*)d_in[8];
    const float* Wa2 = (const float*)d_in[9];
    const float* ba2 = (const float*)d_in[10];
    const int* ei = (const int*)d_in[11];
    float* out = (float*)d_out;

    const int TOT4 = (N_NODES * S_DIM + N_NODES * V_DIM * 3) / 4;
    init_out_kernel<<<(TOT4 + 255) / 256, 256>>>(scalars, vectors, out);
    table_kernel<<<RAW_ROWS, 160>>>(W1, b1, W2, b2, Wa1);
    pack_kernel<<<PK_ROWS, 320>>>();
    proj_kernel<<<N_NODES / PROJ_NB, 256>>>(scalars, vectors, Wa1, ba1);
    edge_kernel<<<2500, 256>>>(edge_vec, ei, Wa2, ba2, out);
}